// round 1
// baseline (speedup 1.0000x reference)
#include <cuda_runtime.h>
#include <cuda_bf16.h>

// Repara_PhC: permittivity = sigmoid((Z - 0.5)/T), Z[i][j] = sum_h gauss_h(x_i,y_j)
// Separable: Z = Fx^T * Fy  (rank-96), Fx[h][i] = exp(-(x_i-x0_h)^2/(2 s_h^2)), etc.
//
// Stage 1: precompute Fx, Fy (96 x 4001, padded to pitch 4096 with zeros).
// Stage 2: tiled outer-product GEMM (64x64 tile / 256 threads / 4x4 microtile)
//          with fused sigmoid epilogue.

#define GN    4001
#define KH    96
#define PITCH 4096
#define TILE  64

__device__ float g_Fx[KH * PITCH];
__device__ float g_Fy[KH * PITCH];

__global__ void precompute_factors(const float* __restrict__ holes) {
    int i = blockIdx.x * blockDim.x + threadIdx.x;   // grid index, 0..PITCH-1
    int h = blockIdx.y;                               // hole, 0..95
    int which = blockIdx.z;                           // 0 = Fx (x0), 1 = Fy (y0)
    if (i >= PITCH) return;
    float c = holes[h * 3 + (which ? 1 : 0)];
    float s = holes[h * 3 + 2];
    float inv2s2 = 1.0f / (2.0f * s * s);
    float v = 0.0f;
    if (i < GN) {
        float g = -10.0f + 0.005f * (float)i;         // linspace(-10,10,4001)
        float d = g - c;
        v = __expf(-d * d * inv2s2);
    }
    if (which == 0) g_Fx[h * PITCH + i] = v;
    else            g_Fy[h * PITCH + i] = v;
}

__global__ __launch_bounds__(256) void gemm_sigmoid(const float* __restrict__ Tptr,
                                                    float* __restrict__ out) {
    __shared__ float As[KH][TILE];   // Fx slice: [k][i_local]
    __shared__ float Bs[KH][TILE];   // Fy slice: [k][j_local]

    const int i0 = blockIdx.y * TILE;
    const int j0 = blockIdx.x * TILE;
    const int tid = threadIdx.x;

    // Cooperative load: 96*64 floats per tile per operand, float4 granularity.
    // Fx/Fy are zero-padded to PITCH=4096 so no bounds checks needed here.
    for (int idx = tid; idx < KH * (TILE / 4); idx += 256) {
        int k = idx >> 4;          // / (TILE/4)
        int v = idx & 15;          // % (TILE/4)
        *(float4*)&As[k][v * 4] = *(const float4*)&g_Fx[k * PITCH + i0 + v * 4];
        *(float4*)&Bs[k][v * 4] = *(const float4*)&g_Fy[k * PITCH + j0 + v * 4];
    }
    __syncthreads();

    const int tx = tid & 15;       // 16 column-groups of 4 j
    const int ty = tid >> 4;       // 16 row-groups   of 4 i

    float acc00 = 0.f, acc01 = 0.f, acc02 = 0.f, acc03 = 0.f;
    float acc10 = 0.f, acc11 = 0.f, acc12 = 0.f, acc13 = 0.f;
    float acc20 = 0.f, acc21 = 0.f, acc22 = 0.f, acc23 = 0.f;
    float acc30 = 0.f, acc31 = 0.f, acc32 = 0.f, acc33 = 0.f;

    #pragma unroll 8
    for (int k = 0; k < KH; ++k) {
        float4 a = *(const float4*)&As[k][ty * 4];
        float4 b = *(const float4*)&Bs[k][tx * 4];
        acc00 = fmaf(a.x, b.x, acc00);
        acc01 = fmaf(a.x, b.y, acc01);
        acc02 = fmaf(a.x, b.z, acc02);
        acc03 = fmaf(a.x, b.w, acc03);
        acc10 = fmaf(a.y, b.x, acc10);
        acc11 = fmaf(a.y, b.y, acc11);
        acc12 = fmaf(a.y, b.z, acc12);
        acc13 = fmaf(a.y, b.w, acc13);
        acc20 = fmaf(a.z, b.x, acc20);
        acc21 = fmaf(a.z, b.y, acc21);
        acc22 = fmaf(a.z, b.z, acc22);
        acc23 = fmaf(a.z, b.w, acc23);
        acc30 = fmaf(a.w, b.x, acc30);
        acc31 = fmaf(a.w, b.y, acc31);
        acc32 = fmaf(a.w, b.z, acc32);
        acc33 = fmaf(a.w, b.w, acc33);
    }

    const float invT = 1.0f / (*Tptr);
    float accs[4][4] = {
        {acc00, acc01, acc02, acc03},
        {acc10, acc11, acc12, acc13},
        {acc20, acc21, acc22, acc23},
        {acc30, acc31, acc32, acc33},
    };

    #pragma unroll
    for (int ii = 0; ii < 4; ++ii) {
        int i = i0 + ty * 4 + ii;
        if (i >= GN) continue;
        size_t rowbase = (size_t)i * GN;
        #pragma unroll
        for (int jj = 0; jj < 4; ++jj) {
            int j = j0 + tx * 4 + jj;
            if (j >= GN) continue;
            float z = (accs[ii][jj] - 0.5f) * invT;
            out[rowbase + j] = 1.0f / (1.0f + __expf(-z));
        }
    }
}

extern "C" void kernel_launch(void* const* d_in, const int* in_sizes, int n_in,
                              void* d_out, int out_size) {
    const float* holes = (const float*)d_in[0];   // (12,8,3) -> 96 x (x0,y0,sigma)
    const float* Tptr  = (const float*)d_in[1];   // scalar T
    float* out = (float*)d_out;                   // 4001 x 4001 fp32

    {
        dim3 grid((PITCH + 255) / 256, KH, 2);
        precompute_factors<<<grid, 256>>>(holes);
    }
    {
        dim3 grid((GN + TILE - 1) / TILE, (GN + TILE - 1) / TILE);  // 63 x 63
        gemm_sigmoid<<<grid, 256>>>(Tptr, out);
    }
}